// round 4
// baseline (speedup 1.0000x reference)
#include <cuda_runtime.h>
#include <cuda_bf16.h>
#include <cstdint>

#define T_STEPS 512
#define BATCH   256
#define NH      512
#define NH2     256
#define NU      32
#define NY      64
#define TT      16

// X split-bf16 planes, K-INTERLEAVED layout: position 2*h2 = real(h2), 2*h2+1 = imag(h2)
__device__ __nv_bfloat16 g_Xh[(size_t)(T_STEPS + 1) * BATCH * NH];
__device__ __nv_bfloat16 g_Xl[(size_t)(T_STEPS + 1) * BATCH * NH];
__device__ __nv_bfloat16 g_Wh[NY * NH];   // same K permutation
__device__ __nv_bfloat16 g_Wl[NY * NH];

// ===================== helpers =====================
__device__ __forceinline__ uint32_t smem_u32(const void* p) {
    uint32_t a;
    asm("{ .reg .u64 t; cvta.to.shared.u64 t, %1; cvt.u32.u64 %0, t; }" : "=r"(a) : "l"(p));
    return a;
}
__device__ __forceinline__ unsigned long long pack2(float lo, float hi) {
    unsigned long long r;
    asm("mov.b64 %0, {%1, %2};" : "=l"(r) : "f"(lo), "f"(hi));
    return r;
}
__device__ __forceinline__ void unpack2(unsigned long long v, float& lo, float& hi) {
    asm("mov.b64 {%0, %1}, %2;" : "=f"(lo), "=f"(hi) : "l"(v));
}
__device__ __forceinline__ unsigned long long fma2(unsigned long long a,
                                                   unsigned long long b,
                                                   unsigned long long c) {
    unsigned long long d;
    asm("fma.rn.f32x2 %0, %1, %2, %3;" : "=l"(d) : "l"(a), "l"(b), "l"(c));
    return d;
}
__device__ __forceinline__ unsigned long long dup2(float v) { return pack2(v, v); }

// pack (lo_val -> low16, hi_val -> high16) as bf16x2
__device__ __forceinline__ uint32_t bf16x2_of(float lo_val, float hi_val) {
    uint32_t r;
    asm("cvt.rn.bf16x2.f32 %0, %1, %2;" : "=r"(r) : "f"(hi_val), "f"(lo_val));
    return r;
}

__device__ __forceinline__ void cpa16(uint32_t dst, const void* src) {
    asm volatile("cp.async.cg.shared.global [%0], [%1], 16;" :: "r"(dst), "l"(src));
}
__device__ __forceinline__ void cp_commit() {
    asm volatile("cp.async.commit_group;" ::: "memory");
}
template <int N>
__device__ __forceinline__ void cp_wait() {
    asm volatile("cp.async.wait_group %0;" :: "n"(N) : "memory");
}
__device__ __forceinline__ void ldsm4(uint32_t& r0, uint32_t& r1, uint32_t& r2, uint32_t& r3,
                                      uint32_t addr) {
    asm volatile("ldmatrix.sync.aligned.m8n8.x4.shared.b16 {%0,%1,%2,%3}, [%4];"
                 : "=r"(r0), "=r"(r1), "=r"(r2), "=r"(r3) : "r"(addr));
}
__device__ __forceinline__ void mma16816(float* c, const uint32_t* a, const uint32_t* b) {
    asm volatile(
        "mma.sync.aligned.m16n8k16.row.col.f32.bf16.bf16.f32 "
        "{%0,%1,%2,%3}, {%4,%5,%6,%7}, {%8,%9}, {%0,%1,%2,%3};"
        : "+f"(c[0]), "+f"(c[1]), "+f"(c[2]), "+f"(c[3])
        : "r"(a[0]), "r"(a[1]), "r"(a[2]), "r"(a[3]), "r"(b[0]), "r"(b[1]));
}

// ========== K2: x0 + fused Bu einsum + complex scan -> split-bf16 X ==========
// grid = 2*BATCH + 1. Last block performs the W split/permute (for k3).
__global__ void __launch_bounds__(128)
k2_scan(const float* __restrict__ U,
        const float* __restrict__ lr_,
        const float* __restrict__ li_,
        const float* __restrict__ B,
        const float* __restrict__ y0,
        const float* __restrict__ Wyx,
        const float* __restrict__ byx,
        const float* __restrict__ Wxy) {
    const int tid = threadIdx.x;

    if (blockIdx.x == 2 * BATCH) {
        // ---- W split + K-interleave permutation ----
        for (int i = tid; i < NY * NH2; i += 128) {
            int n  = i >> 8;
            int h2 = i & 255;
            float wr = Wxy[(size_t)n * NH + h2];
            float wi = Wxy[(size_t)n * NH + NH2 + h2];
            uint32_t hw = bf16x2_of(wr, wi);
            float wr_h = __uint_as_float(hw << 16);
            float wi_h = __uint_as_float(hw & 0xFFFF0000u);
            uint32_t lw = bf16x2_of(wr - wr_h, wi - wi_h);
            size_t o = (size_t)n * NH + 2 * h2;
            *(uint32_t*)&g_Wh[o] = hw;
            *(uint32_t*)&g_Wl[o] = lw;
        }
        return;
    }

    __shared__ unsigned long long Us2[TT][NU];
    __shared__ float ys[NY];
    const int b     = blockIdx.x >> 1;
    const int chalf = blockIdx.x & 1;
    const int h2    = chalf * 128 + tid;

    // ---- x0 = y0 @ Wyx^T + byx for pair (h2, h2+256) ----
    if (tid < NY) ys[tid] = y0[b * NY + tid];
    __syncthreads();
    unsigned long long acc0 = pack2(byx[h2], byx[h2 + NH2]);
    {
        const float4* wr = (const float4*)(Wyx + (size_t)h2 * NY);
        const float4* wi = (const float4*)(Wyx + (size_t)(h2 + NH2) * NY);
#pragma unroll
        for (int q = 0; q < NY / 4; q++) {
            float4 a = wr[q], c = wi[q];
            acc0 = fma2(pack2(a.x, c.x), dup2(ys[4 * q + 0]), acc0);
            acc0 = fma2(pack2(a.y, c.y), dup2(ys[4 * q + 1]), acc0);
            acc0 = fma2(pack2(a.z, c.z), dup2(ys[4 * q + 2]), acc0);
            acc0 = fma2(pack2(a.w, c.w), dup2(ys[4 * q + 3]), acc0);
        }
    }
    float xr, xi;
    unpack2(acc0, xr, xi);
    {
        size_t o = (size_t)b * NH + 2 * h2;
        uint32_t hp = bf16x2_of(xr, xi);
        float rh = __uint_as_float(hp << 16);
        float ih = __uint_as_float(hp & 0xFFFF0000u);
        *(uint32_t*)&g_Xh[o] = hp;
        *(uint32_t*)&g_Xl[o] = bf16x2_of(xr - rh, xi - ih);
    }

    // ---- B rows packed (re, im) ----
    unsigned long long bb2[NU];
    const float* brp = B + (size_t)h2 * NU;
    const float* bip = B + (size_t)(h2 + NH2) * NU;
#pragma unroll
    for (int q = 0; q < NU / 4; q++) {
        float4 r = *(const float4*)(brp + 4 * q);
        float4 i = *(const float4*)(bip + 4 * q);
        bb2[4 * q + 0] = pack2(r.x, i.x);
        bb2[4 * q + 1] = pack2(r.y, i.y);
        bb2[4 * q + 2] = pack2(r.z, i.z);
        bb2[4 * q + 3] = pack2(r.w, i.w);
    }
    const float lam_r = lr_[h2];
    const float lam_i = li_[h2];

    for (int t0 = 0; t0 < T_STEPS; t0 += TT) {
        __syncthreads();
#pragma unroll
        for (int r = 0; r < (TT * NU) / 128; r++) {
            int i  = tid + 128 * r;
            int tt = i >> 5;
            int u  = i & 31;
            float v = U[((size_t)(t0 + tt) * BATCH + b) * NU + u];
            Us2[tt][u] = pack2(v, v);
        }
        __syncthreads();
#pragma unroll 4
        for (int tt = 0; tt < TT; tt++) {
            unsigned long long accA = 0ULL, accB = 0ULL;
#pragma unroll
            for (int u = 0; u < NU; u += 2) {
                accA = fma2(Us2[tt][u + 0], bb2[u + 0], accA);
                accB = fma2(Us2[tt][u + 1], bb2[u + 1], accB);
            }
            float ar, ai, br_, bi_;
            unpack2(accA, ar, ai);
            unpack2(accB, br_, bi_);
            const float bur = ar + br_;
            const float bui = ai + bi_;
            const float nr = fmaf(lam_r, xr, fmaf(-lam_i, xi, bur));
            const float ni = fmaf(lam_i, xr, fmaf(lam_r, xi, bui));
            xr = nr; xi = ni;
            size_t o = ((size_t)(t0 + tt + 1) * BATCH + b) * NH + 2 * h2;
            uint32_t hp = bf16x2_of(xr, xi);
            float rh = __uint_as_float(hp << 16);
            float ih = __uint_as_float(hp & 0xFFFF0000u);
            *(uint32_t*)&g_Xh[o] = hp;
            *(uint32_t*)&g_Xl[o] = bf16x2_of(xr - rh, xi - ih);
        }
    }
}

// ========== K3: HMMA bf16x3 GEMM: Y[t, 256, 64] = X @ W^T + bias ==========
// CTA = one timestep t, 256 threads, M=256 tile, K=512 in 8 chunks of 64.
#define KC        64
#define NCH       8
#define A_STRIDE  144          // 64 bf16 (128B) + 16B pad: conflict-free ldmatrix
#define SM_BIAS   0
#define STAGE_SZ  92160        // Ah(36864)+Al(36864)+Wh(9216)+Wl(9216)
#define SM_AH(s)  (512 + (s) * STAGE_SZ)
#define SM_AL(s)  (SM_AH(s) + 36864)
#define SM_WH(s)  (SM_AH(s) + 73728)
#define SM_WL(s)  (SM_AH(s) + 82944)
#define SMEM_K3   (512 + 2 * STAGE_SZ)

__global__ void __launch_bounds__(256, 1)
k3_mma(const float* __restrict__ bias, float* __restrict__ Y) {
    extern __shared__ char smem[];
    const uint32_t sb = smem_u32(smem);
    const int tid  = threadIdx.x;
    const int wid  = tid >> 5;          // 0..7, owns 32 M-rows
    const int lane = tid & 31;
    const int t    = blockIdx.x;

    float* s_bias = (float*)(smem + SM_BIAS);
    if (tid < NY) s_bias[tid] = bias[tid];

    const size_t Abase = (size_t)t * BATCH * NH;
    const int lrow = tid >> 3;          // 0..31
    const int lseg = tid & 7;           // 16B segment

    auto stage_load = [&](int c) {
        const int s = c & 1;
        const __nv_bfloat16* ah = g_Xh + Abase + c * KC;
        const __nv_bfloat16* al = g_Xl + Abase + c * KC;
#pragma unroll
        for (int p = 0; p < 8; p++) {           // 256 rows
            int row = p * 32 + lrow;
            uint32_t d = row * A_STRIDE + lseg * 16;
            cpa16(sb + SM_AH(s) + d, ah + (size_t)row * NH + lseg * 8);
            cpa16(sb + SM_AL(s) + d, al + (size_t)row * NH + lseg * 8);
        }
        const __nv_bfloat16* wh = g_Wh + c * KC;
        const __nv_bfloat16* wl = g_Wl + c * KC;
#pragma unroll
        for (int p = 0; p < 2; p++) {           // 64 rows
            int row = p * 32 + lrow;
            uint32_t d = row * A_STRIDE + lseg * 16;
            cpa16(sb + SM_WH(s) + d, wh + (size_t)row * NH + lseg * 8);
            cpa16(sb + SM_WL(s) + d, wl + (size_t)row * NH + lseg * 8);
        }
        cp_commit();
    };

    float acc[2][8][4];
#pragma unroll
    for (int mt = 0; mt < 2; mt++)
#pragma unroll
        for (int nt = 0; nt < 8; nt++)
#pragma unroll
            for (int e = 0; e < 4; e++) acc[mt][nt][e] = 0.0f;

    // ldmatrix lane addressing
    const int arow = wid * 32 + (lane & 15);
    const int akb  = (lane >> 4) * 16;
    const uint32_t aOff = arow * A_STRIDE + akb;
    const int wmat = lane >> 3;
    const int wrow_in = (lane & 7) + ((wmat >> 1) << 3);
    const int wkb  = (wmat & 1) * 16;
    const uint32_t wOff = wrow_in * A_STRIDE + wkb;

    stage_load(0);

#pragma unroll 1
    for (int c = 0; c < NCH; c++) {
        const int s = c & 1;
        if (c + 1 < NCH) { stage_load(c + 1); cp_wait<1>(); }
        else             { cp_wait<0>(); }
        __syncthreads();

#pragma unroll
        for (int ks = 0; ks < 4; ks++) {
            const uint32_t ko = ks * 32;
            uint32_t ahf[2][4], alf[2][4];
#pragma unroll
            for (int mt = 0; mt < 2; mt++) {
                uint32_t aA = sb + SM_AH(s) + aOff + mt * (16 * A_STRIDE) + ko;
                ldsm4(ahf[mt][0], ahf[mt][1], ahf[mt][2], ahf[mt][3], aA);
                uint32_t aL = sb + SM_AL(s) + aOff + mt * (16 * A_STRIDE) + ko;
                ldsm4(alf[mt][0], alf[mt][1], alf[mt][2], alf[mt][3], aL);
            }
            uint32_t whf[8][2], wlf[8][2];
#pragma unroll
            for (int g = 0; g < 4; g++) {
                uint32_t r0, r1, r2, r3;
                uint32_t wA = sb + SM_WH(s) + wOff + g * (16 * A_STRIDE) + ko;
                ldsm4(r0, r1, r2, r3, wA);
                whf[2 * g][0] = r0; whf[2 * g][1] = r1;
                whf[2 * g + 1][0] = r2; whf[2 * g + 1][1] = r3;
                uint32_t wL = sb + SM_WL(s) + wOff + g * (16 * A_STRIDE) + ko;
                ldsm4(r0, r1, r2, r3, wL);
                wlf[2 * g][0] = r0; wlf[2 * g][1] = r1;
                wlf[2 * g + 1][0] = r2; wlf[2 * g + 1][1] = r3;
            }
#pragma unroll
            for (int mt = 0; mt < 2; mt++)
#pragma unroll
                for (int nt = 0; nt < 8; nt++) {
                    mma16816(acc[mt][nt], ahf[mt], whf[nt]);   // Ah*Wh
                    mma16816(acc[mt][nt], ahf[mt], wlf[nt]);   // Ah*Wl
                    mma16816(acc[mt][nt], alf[mt], whf[nt]);   // Al*Wh
                }
        }
        __syncthreads();
    }

    // ---- epilogue ----
    const int r0base = wid * 32 + (lane >> 2);
    const int coff   = (lane & 3) * 2;
#pragma unroll
    for (int mt = 0; mt < 2; mt++) {
#pragma unroll
        for (int nt = 0; nt < 8; nt++) {
            const int cb = nt * 8 + coff;
            const float b0 = s_bias[cb], b1 = s_bias[cb + 1];
            const int ra = r0base + mt * 16;
            float* y0p = Y + ((size_t)t * BATCH + ra) * NY + cb;
            float* y1p = Y + ((size_t)t * BATCH + ra + 8) * NY + cb;
            *(float2*)y0p = make_float2(acc[mt][nt][0] + b0, acc[mt][nt][1] + b1);
            *(float2*)y1p = make_float2(acc[mt][nt][2] + b0, acc[mt][nt][3] + b1);
        }
    }
}

extern "C" void kernel_launch(void* const* d_in, const int* in_sizes, int n_in,
                              void* d_out, int out_size) {
    (void)in_sizes; (void)n_in; (void)out_size;
    const float* y0  = (const float*)d_in[0];
    const float* U   = (const float*)d_in[1];
    const float* lr  = (const float*)d_in[2];
    const float* li  = (const float*)d_in[3];
    const float* B   = (const float*)d_in[4];
    const float* Wyx = (const float*)d_in[5];
    const float* byx = (const float*)d_in[6];
    const float* Wxy = (const float*)d_in[7];
    const float* bxy = (const float*)d_in[8];
    float* Y = (float*)d_out;

    static bool attr_done = false;
    if (!attr_done) {
        cudaFuncSetAttribute(k3_mma, cudaFuncAttributeMaxDynamicSharedMemorySize, SMEM_K3);
        attr_done = true;
    }

    k2_scan<<<2 * BATCH + 1, 128>>>(U, lr, li, B, y0, Wyx, byx, Wxy);
    k3_mma<<<T_STEPS + 1, 256, SMEM_K3>>>(bxy, Y);
}